// round 2
// baseline (speedup 1.0000x reference)
#include <cuda_runtime.h>
#include <math.h>

// VectorQuantizer: N=65536 points (B=64,H=32,W=32 flattened BHWC), C=64, K=1024.
// Output layout (float32): [quantized 4194304][vq_loss 1][indices 65536][perplexity 1]
//
// Numerics (verified bit-exact vs reference in R1):
//  - dot(x,e_k): sequential-c fp32 FMA, single accumulator
//  - a = sum(x*x): sequential-c fp32 rn(mul)+rn(add)
//  - d = rn( rn(a - rn(2*dot)) + esq_k ); argmin first-index tie-break
//  - quantized_st = rn(x + rn(q - x))

#define NPTS   65536
#define KC     1024
#define CD     64
#define HW     1024
#define MT     128

#define XDP 264   // xs dup'd row pitch (floats): 128 pts * 2 + 8 pad (1056B, 16B aligned)
#define EP  132   // es row pitch (floats): 128 + 4 pad (528B, 16B aligned)
#define SMEM_FLOATS (CD*XDP + CD*EP + 128)
#define SMEM_BYTES  (SMEM_FLOATS * 4)

#define OFF_LOSS  4194304
#define OFF_IDX   4194305
#define OFF_PERP  4259841

typedef unsigned long long u64;

__device__ float        g_esq[KC];
__device__ int          g_idx[NPTS];
__device__ unsigned int g_hist[KC];
__device__ double       g_loss;

__device__ __forceinline__ void unpack2(u64 v, float &lo, float &hi) {
    asm("mov.b64 {%0, %1}, %2;" : "=f"(lo), "=f"(hi) : "l"(v));
}
// packed fp32x2 FMA: each lane is IEEE-rn fp32 FMA (bit-identical to scalar FFMA)
__device__ __forceinline__ void ffma2(u64 &acc, u64 a, u64 b) {
    asm("fma.rn.f32x2 %0, %1, %2, %0;" : "+l"(acc) : "l"(a), "l"(b));
}

// ---------------- init ----------------
__global__ void vq_init() {
    int t = blockIdx.x * blockDim.x + threadIdx.x;
    if (t < KC) g_hist[t] = 0u;
    if (t == 0) g_loss = 0.0;
}

// ---------------- esq[k] = sum_c e^2 (sequential fp32) ----------------
__global__ void vq_esq(const float* __restrict__ emb) {
    int k = blockIdx.x * blockDim.x + threadIdx.x;
    if (k < KC) {
        float s = 0.0f;
        const float* er = emb + (size_t)k * CD;
        #pragma unroll
        for (int c = 0; c < CD; ++c) {
            float e = er[c];
            s = __fadd_rn(s, __fmul_rn(e, e));
        }
        g_esq[k] = s;
    }
}

// ---------------- main: distances + argmin (+ idx/hist outputs) ----------------
__global__ void __launch_bounds__(256, 2) vq_main(const float* __restrict__ inputs,
                                                  const float* __restrict__ emb,
                                                  float* __restrict__ outIdxF) {
    extern __shared__ float sm[];
    float* xs  = sm;                 // [CD][XDP]  x duplicated: (x,x) per point
    float* es  = sm + CD * XDP;      // [CD][EP]   e transposed + unit-interleaved
    float* as_ = es + CD * EP;       // [128]

    const int t  = threadIdx.x;
    const int tr = t >> 4;    // 0..15 point group (8 pts each)
    const int tc = t & 15;    // 0..15 code group (8 codes each)
    const int n0 = blockIdx.x * MT;
    const int b  = n0 >> 10;
    const int p0 = n0 & 1023;
    const float* xbase = inputs + (size_t)b * (CD * HW) + p0;

    // ---- load x tile, duplicated pairwise: xs[c][2p]=xs[c][2p+1]=x[c][p]
    #pragma unroll
    for (int j = 0; j < 8; ++j) {
        int q = t + j * 256;
        int c = q >> 5;
        int g = q & 31;
        float4 v = *reinterpret_cast<const float4*>(xbase + (size_t)c * HW + 4 * g);
        float4 d0 = make_float4(v.x, v.x, v.y, v.y);
        float4 d1 = make_float4(v.z, v.z, v.w, v.w);
        *reinterpret_cast<float4*>(&xs[c * XDP + 8 * g])     = d0;
        *reinterpret_cast<float4*>(&xs[c * XDP + 8 * g + 4]) = d1;
    }
    __syncthreads();

    // ---- a = ||x||^2 : strictly sequential fp32
    if (t < MT) {
        float s = 0.0f;
        #pragma unroll
        for (int c = 0; c < CD; ++c) {
            float xv = xs[c * XDP + 2 * t];
            s = __fadd_rn(s, __fmul_rn(xv, xv));
        }
        as_[t] = s;
    }

    float bestv[8];
    int   besti[8];
    #pragma unroll
    for (int i = 0; i < 8; ++i) { bestv[i] = __int_as_float(0x7f800000); besti[i] = 0x7fffffff; }

    #pragma unroll 1
    for (int kc = 0; kc < 8; ++kc) {
        __syncthreads();   // es reuse (and as_/xs visibility on first iter)
        // load e chunk transposed: code k, channel c -> es[c][f(k)]
        // f(k) = ((k&4)<<4) | ((k>>3)<<2) | (k&3)  (code-pair unit interleave)
        #pragma unroll
        for (int j = 0; j < 8; ++j) {
            int q  = t + j * 256;
            int k  = q & 127;
            int cg = q >> 7;          // 0..15
            float4 v = *reinterpret_cast<const float4*>(emb + (size_t)(kc * 128 + k) * CD + cg * 4);
            int fo = ((k & 4) << 4) | ((k >> 3) << 2) | (k & 3);
            es[(cg * 4 + 0) * EP + fo] = v.x;
            es[(cg * 4 + 1) * EP + fo] = v.y;
            es[(cg * 4 + 2) * EP + fo] = v.z;
            es[(cg * 4 + 3) * EP + fo] = v.w;
        }
        __syncthreads();

        u64 acc[8][4];
        #pragma unroll
        for (int p = 0; p < 8; ++p)
            #pragma unroll
            for (int q = 0; q < 4; ++q) acc[p][q] = 0ULL;

        const float* esr = es + 4 * tc;
        const float* xsr = xs + 16 * tr;

        #pragma unroll 2
        for (int c = 0; c < CD; ++c) {
            // e: codes tc*8 + {0,1},{2,3} in E0, {4,5},{6,7} in E1 — pre-paired
            ulonglong2 E0 = *reinterpret_cast<const ulonglong2*>(esr + c * EP);
            ulonglong2 E1 = *reinterpret_cast<const ulonglong2*>(esr + c * EP + 64);
            // x: 8 points, each duplicated (x,x)
            ulonglong2 X0 = *reinterpret_cast<const ulonglong2*>(xsr + c * XDP);
            ulonglong2 X1 = *reinterpret_cast<const ulonglong2*>(xsr + c * XDP + 4);
            ulonglong2 X2 = *reinterpret_cast<const ulonglong2*>(xsr + c * XDP + 8);
            ulonglong2 X3 = *reinterpret_cast<const ulonglong2*>(xsr + c * XDP + 12);

            ffma2(acc[0][0], X0.x, E0.x); ffma2(acc[0][1], X0.x, E0.y);
            ffma2(acc[0][2], X0.x, E1.x); ffma2(acc[0][3], X0.x, E1.y);
            ffma2(acc[1][0], X0.y, E0.x); ffma2(acc[1][1], X0.y, E0.y);
            ffma2(acc[1][2], X0.y, E1.x); ffma2(acc[1][3], X0.y, E1.y);
            ffma2(acc[2][0], X1.x, E0.x); ffma2(acc[2][1], X1.x, E0.y);
            ffma2(acc[2][2], X1.x, E1.x); ffma2(acc[2][3], X1.x, E1.y);
            ffma2(acc[3][0], X1.y, E0.x); ffma2(acc[3][1], X1.y, E0.y);
            ffma2(acc[3][2], X1.y, E1.x); ffma2(acc[3][3], X1.y, E1.y);
            ffma2(acc[4][0], X2.x, E0.x); ffma2(acc[4][1], X2.x, E0.y);
            ffma2(acc[4][2], X2.x, E1.x); ffma2(acc[4][3], X2.x, E1.y);
            ffma2(acc[5][0], X2.y, E0.x); ffma2(acc[5][1], X2.y, E0.y);
            ffma2(acc[5][2], X2.y, E1.x); ffma2(acc[5][3], X2.y, E1.y);
            ffma2(acc[6][0], X3.x, E0.x); ffma2(acc[6][1], X3.x, E0.y);
            ffma2(acc[6][2], X3.x, E1.x); ffma2(acc[6][3], X3.x, E1.y);
            ffma2(acc[7][0], X3.y, E0.x); ffma2(acc[7][1], X3.y, E0.y);
            ffma2(acc[7][2], X3.y, E1.x); ffma2(acc[7][3], X3.y, E1.y);
        }

        // epilogue: d = (a - 2*dot) + esq, argmin with first-index ties
        #pragma unroll
        for (int q = 0; q < 4; ++q) {
            int kbase = kc * 128 + tc * 8 + 2 * q;
            float2 eq = *reinterpret_cast<const float2*>(&g_esq[kbase]);
            #pragma unroll
            for (int p = 0; p < 8; ++p) {
                float dlo, dhi; unpack2(acc[p][q], dlo, dhi);
                float a = as_[tr * 8 + p];
                float dd0 = __fadd_rn(__fsub_rn(a, __fmul_rn(2.0f, dlo)), eq.x);
                float dd1 = __fadd_rn(__fsub_rn(a, __fmul_rn(2.0f, dhi)), eq.y);
                if (dd0 < bestv[p]) { bestv[p] = dd0; besti[p] = kbase; }
                if (dd1 < bestv[p]) { bestv[p] = dd1; besti[p] = kbase + 1; }
            }
        }
    }

    // cross-lane argmin over the 16 code lanes
    #pragma unroll
    for (int off = 1; off < 16; off <<= 1) {
        #pragma unroll
        for (int i = 0; i < 8; ++i) {
            float ov = __shfl_xor_sync(0xffffffffu, bestv[i], off);
            int   oi = __shfl_xor_sync(0xffffffffu, besti[i], off);
            if (ov < bestv[i] || (ov == bestv[i] && oi < besti[i])) { bestv[i] = ov; besti[i] = oi; }
        }
    }
    if (tc == 0) {
        #pragma unroll
        for (int i = 0; i < 8; ++i) {
            int n = n0 + tr * 8 + i;
            g_idx[n]   = besti[i];
            outIdxF[n] = (float)besti[i];
            atomicAdd(&g_hist[besti[i]], 1u);
        }
    }
}

// ---------------- quantize + loss (coalesced via smem transpose) ----------------
__global__ void __launch_bounds__(256) vq_quant(const float* __restrict__ inputs,
                                                const float* __restrict__ emb,
                                                float* __restrict__ outQ) {
    __shared__ float  xt[CD * 129];   // [c][p], pitch 129 -> conflict-light both ways
    __shared__ double red[256];

    const int t  = threadIdx.x;
    const int n0 = blockIdx.x * MT;
    const int b  = n0 >> 10;
    const int p0 = n0 & 1023;
    const float* xbase = inputs + (size_t)b * (CD * HW) + p0;

    #pragma unroll
    for (int j = 0; j < 8; ++j) {
        int q = t + j * 256;
        int c = q >> 5;
        int g = q & 31;
        float4 v = *reinterpret_cast<const float4*>(xbase + (size_t)c * HW + 4 * g);
        xt[c * 129 + 4 * g + 0] = v.x;
        xt[c * 129 + 4 * g + 1] = v.y;
        xt[c * 129 + 4 * g + 2] = v.z;
        xt[c * 129 + 4 * g + 3] = v.w;
    }
    __syncthreads();

    const int pc = t & 15;   // channel group (4 floats)
    const int pg = t >> 4;   // point group (8 points)
    double s = 0.0;

    #pragma unroll
    for (int i = 0; i < 8; ++i) {
        int p = pg * 8 + i;
        int n = n0 + p;
        int ki = g_idx[n];
        float4 qv = __ldg(reinterpret_cast<const float4*>(emb + (size_t)ki * CD + 4 * pc));
        float x0 = xt[(4 * pc + 0) * 129 + p];
        float x1 = xt[(4 * pc + 1) * 129 + p];
        float x2 = xt[(4 * pc + 2) * 129 + p];
        float x3 = xt[(4 * pc + 3) * 129 + p];

        float e0 = __fsub_rn(qv.x, x0);
        float e1 = __fsub_rn(qv.y, x1);
        float e2 = __fsub_rn(qv.z, x2);
        float e3 = __fsub_rn(qv.w, x3);

        float4 o;  // straight-through: x + (q - x)
        o.x = __fadd_rn(x0, e0);
        o.y = __fadd_rn(x1, e1);
        o.z = __fadd_rn(x2, e2);
        o.w = __fadd_rn(x3, e3);
        *reinterpret_cast<float4*>(outQ + (size_t)n * CD + 4 * pc) = o;

        s += (double)__fmul_rn(e0, e0) + (double)__fmul_rn(e1, e1)
           + (double)__fmul_rn(e2, e2) + (double)__fmul_rn(e3, e3);
    }

    red[t] = s;
    __syncthreads();
    for (int off = 128; off > 0; off >>= 1) {
        if (t < off) red[t] += red[t + off];
        __syncthreads();
    }
    if (t == 0) atomicAdd(&g_loss, red[0]);
}

// ---------------- finalize: loss + perplexity ----------------
__global__ void vq_final(float* __restrict__ out) {
    __shared__ double red[256];
    int t = threadIdx.x;
    double s = 0.0;
    for (int k = t; k < KC; k += 256) {
        float cnt = (float)g_hist[k];
        float pr  = __fmul_rn(cnt, 1.0f / 65536.0f);
        float lg  = logf(__fadd_rn(pr, 1e-10f));
        s += (double)__fmul_rn(pr, lg);
    }
    red[t] = s;
    __syncthreads();
    for (int off = 128; off > 0; off >>= 1) {
        if (t < off) red[t] += red[t + off];
        __syncthreads();
    }
    if (t == 0) {
        float m    = (float)(g_loss / 4194304.0);
        float loss = __fadd_rn(m, __fmul_rn(0.25f, m));
        out[OFF_LOSS] = loss;
        float S = (float)red[0];
        out[OFF_PERP] = expf(-S);
    }
}

extern "C" void kernel_launch(void* const* d_in, const int* in_sizes, int n_in,
                              void* d_out, int out_size) {
    const float* inputs = (const float*)d_in[0];
    const float* emb    = (const float*)d_in[1];
    if (n_in >= 2 && in_sizes[0] == KC * CD && in_sizes[1] == NPTS * CD) {
        const float* tmp = inputs; inputs = emb; emb = tmp;
    }
    float* out = (float*)d_out;

    cudaFuncSetAttribute(vq_main, cudaFuncAttributeMaxDynamicSharedMemorySize, SMEM_BYTES);

    vq_init<<<1, 1024>>>();
    vq_esq<<<KC / 256, 256>>>(emb);
    vq_main<<<NPTS / MT, 256, SMEM_BYTES>>>(inputs, emb, out + OFF_IDX);
    vq_quant<<<NPTS / MT, 256>>>(inputs, emb, out);
    vq_final<<<1, 256>>>(out);
}